// round 6
// baseline (speedup 1.0000x reference)
#include <cuda_runtime.h>
#include <stdint.h>

#define DW    32     // D_WORLDS
#define K2D   64     // 2*D_WORLDS
#define NW    512    // N_WORLDS
#define BATCH 2048

// Packed dual-fp32 FMA (sm_100+ PTX-only), accumulate in place
#define FMA2(acc_, a_, b_) \
    asm("fma.rn.f32x2 %0, %1, %2, %0;" : "+l"(acc_) : "l"(a_), "l"(b_))

__global__ __launch_bounds__(256, 3)
void binop_fused_kernel(const float* __restrict__ states,   // [8*2048, 32, 512]
                        const float* __restrict__ W,        // [128, 32, 64]
                        const float* __restrict__ b,        // [128, 32]
                        const int*   __restrict__ indices,  // [2048]
                        const int*   __restrict__ symbols,  // [2048]
                        const int*   __restrict__ args,     // [2048, 2]
                        float*       __restrict__ out)      // [2048, 32, 512]
{
    __shared__ __align__(16) float2 ws2[DW * K2D];   // dup'd W[sym], 16 KB
    __shared__ float bsh[DW];
    __shared__ __align__(16) float4 xs[2][4][128];   // staged x chunks, 16 KB
    __shared__ float sqp[4][64][8];                  // partial sq sums, 8 KB

    const int n  = blockIdx.x;
    const int t  = threadIdx.x;
    const int tg = t >> 6;        // d-group: d = 8*tg .. 8*tg+7
    const int cl = t & 63;        // owns cols {4cl..4cl+3} and {256+4cl..+3}
    const int d0 = tg * 8;
    const int rs = tg;            // staging row within chunk (reuse tg)

    const int idx = indices[n];
    const int sym = symbols[n];
    const int a0  = args[2 * n];
    const int a1  = args[2 * n + 1];

    // Load + duplicate W[sym] into smem
    const float* Wp = W + (size_t)sym * (DW * K2D);
    #pragma unroll
    for (int i = 0; i < 8; i++) {
        int j = t + 256 * i;
        float v = Wp[j];
        ws2[j] = make_float2(v, v);
    }
    if (t < DW) bsh[t] = b[sym * DW + t];

    const float* xl = states + (size_t)(a0 * BATCH + idx) * (DW * NW);
    const float* xr = states + (size_t)(a1 * BATCH + idx) * (DW * NW);

    // acc[dd][p]: packed col-pairs; p=0,1 -> cols 4cl..+3 ; p=2,3 -> 256+4cl..+3
    uint64_t acc[8][4];
    #pragma unroll
    for (int dd = 0; dd < 8; dd++) {
        float bv = bsh[d0 + dd];   // bsh written by t<32 in same... guard: see sync below
        (void)bv;
    }

    // Stage chunk 0 (k rows 0..3, from left state): coalesced, conflict-free
    {
        const float4* p = (const float4*)(xl + (size_t)rs * NW);
        xs[0][rs][cl]      = p[cl];
        xs[0][rs][cl + 64] = p[cl + 64];
    }
    __syncthreads();

    // init accs with bias (after sync so bsh is valid)
    #pragma unroll
    for (int dd = 0; dd < 8; dd++) {
        float bv = bsh[d0 + dd];
        uint64_t pb;
        asm("mov.b64 %0, {%1,%2};" : "=l"(pb) : "f"(bv), "f"(bv));
        acc[dd][0] = pb; acc[dd][1] = pb; acc[dd][2] = pb; acc[dd][3] = pb;
    }

    const float2* wgrp = ws2 + d0 * K2D;

    #pragma unroll 1
    for (int c = 0; c < 16; c++) {
        const int cb = c & 1;

        // Issue next chunk's global loads early (hide DRAM latency under FMAs)
        float4 v0, v1;
        if (c < 15) {
            const int kk = 4 * (c + 1) + rs;
            const float4* p = (const float4*)((kk < 32) ? (xl + (size_t)kk * NW)
                                                        : (xr + (size_t)(kk - 32) * NW));
            v0 = p[cl];
            v1 = p[cl + 64];
        }

        // Compute chunk c: 2 k-pairs x 8 d x 8 FMA2
        const float2* wk0 = wgrp + 4 * c;
        #pragma unroll
        for (int kp = 0; kp < 2; kp++) {
            const ulonglong2 x0a = *(const ulonglong2*)&xs[cb][2 * kp][cl];
            const ulonglong2 x0b = *(const ulonglong2*)&xs[cb][2 * kp][cl + 64];
            const ulonglong2 x1a = *(const ulonglong2*)&xs[cb][2 * kp + 1][cl];
            const ulonglong2 x1b = *(const ulonglong2*)&xs[cb][2 * kp + 1][cl + 64];
            const float2* wk = wk0 + 2 * kp;
            #pragma unroll
            for (int dd = 0; dd < 8; dd++) {
                // Broadcast LDS.128: {dup w[d][k], dup w[d][k+1]}
                ulonglong2 wv = *(const ulonglong2*)(wk + (size_t)dd * K2D);
                FMA2(acc[dd][0], wv.x, x0a.x);
                FMA2(acc[dd][1], wv.x, x0a.y);
                FMA2(acc[dd][2], wv.x, x0b.x);
                FMA2(acc[dd][3], wv.x, x0b.y);
                FMA2(acc[dd][0], wv.y, x1a.x);
                FMA2(acc[dd][1], wv.y, x1a.y);
                FMA2(acc[dd][2], wv.y, x1b.x);
                FMA2(acc[dd][3], wv.y, x1b.y);
            }
        }

        if (c < 15) {
            xs[cb ^ 1][rs][cl]      = v0;
            xs[cb ^ 1][rs][cl + 64] = v1;
        }
        __syncthreads();
    }

    // Partial squared sums over this thread's 8 d's, per column
    float sq[8];
    #pragma unroll
    for (int j = 0; j < 8; j++) sq[j] = 0.f;
    #pragma unroll
    for (int dd = 0; dd < 8; dd++) {
        #pragma unroll
        for (int p = 0; p < 4; p++) {
            float2 v = *(float2*)&acc[dd][p];
            sq[2 * p]     = fmaf(v.x, v.x, sq[2 * p]);
            sq[2 * p + 1] = fmaf(v.y, v.y, sq[2 * p + 1]);
        }
    }
    #pragma unroll
    for (int j = 0; j < 8; j++) sqp[tg][cl][j] = sq[j];
    __syncthreads();

    float s[8];
    #pragma unroll
    for (int j = 0; j < 8; j++) {
        float tot = sqp[0][cl][j] + sqp[1][cl][j] + sqp[2][cl][j] + sqp[3][cl][j];
        s[j] = rsqrtf(fmaxf(tot, 1e-12f));
    }

    // Scatter row = indices[n] (arange -> bijective, plain stores)
    float4* op = (float4*)(out + (size_t)idx * (DW * NW)) + cl;
    #pragma unroll
    for (int dd = 0; dd < 8; dd++) {
        float2 v0 = *(float2*)&acc[dd][0];
        float2 v1 = *(float2*)&acc[dd][1];
        float2 v2 = *(float2*)&acc[dd][2];
        float2 v3 = *(float2*)&acc[dd][3];
        float4 r0 = make_float4(v0.x * s[0], v0.y * s[1], v1.x * s[2], v1.y * s[3]);
        float4 r1 = make_float4(v2.x * s[4], v2.y * s[5], v3.x * s[6], v3.y * s[7]);
        op[(size_t)(d0 + dd) * 128]      = r0;
        op[(size_t)(d0 + dd) * 128 + 64] = r1;
    }
}

extern "C" void kernel_launch(void* const* d_in, const int* in_sizes, int n_in,
                              void* d_out, int out_size) {
    const float* states  = (const float*)d_in[0];
    const float* W       = (const float*)d_in[1];
    const float* b       = (const float*)d_in[2];
    const int*   indices = (const int*)d_in[3];
    const int*   symbols = (const int*)d_in[4];
    const int*   args    = (const int*)d_in[5];
    float*       out     = (float*)d_out;

    binop_fused_kernel<<<BATCH, 256>>>(states, W, b, indices, symbols, args, out);
}

// round 7
// speedup vs baseline: 1.3473x; 1.3473x over previous
#include <cuda_runtime.h>
#include <stdint.h>

#define DW    32     // D_WORLDS
#define K2D   64     // 2*D_WORLDS
#define NW    512    // N_WORLDS
#define BATCH 2048

// Packed dual-fp32 FMA (sm_100+ PTX-only), accumulate in place
#define FMA2(acc_, a_, b_) \
    asm("fma.rn.f32x2 %0, %1, %2, %0;" : "+l"(acc_) : "l"(a_), "l"(b_))

// One k-pair (rows k,k+1) against 8 d's / 4 cols.
// X0 = row k cols (4cl..4cl+3), X1 = row k+1. wk -> &ws2[d0*K2D + k].
__device__ __forceinline__ void proc_kpair(uint64_t acc[8][2],
                                           const ulonglong2 X0, const ulonglong2 X1,
                                           const float2* __restrict__ wk) {
    #pragma unroll
    for (int dd = 0; dd < 8; dd++) {
        // Broadcast LDS.128: {dup w[d][k], dup w[d][k+1]}
        ulonglong2 wv = *(const ulonglong2*)(wk + (size_t)dd * K2D);
        FMA2(acc[dd][0], wv.x, X0.x);
        FMA2(acc[dd][1], wv.x, X0.y);
        FMA2(acc[dd][0], wv.y, X1.x);
        FMA2(acc[dd][1], wv.y, X1.y);
    }
}

__global__ __launch_bounds__(512, 2)
void binop_fused_kernel(const float* __restrict__ states,   // [8*2048, 32, 512]
                        const float* __restrict__ W,        // [128, 32, 64]
                        const float* __restrict__ b,        // [128, 32]
                        const int*   __restrict__ indices,  // [2048]
                        const int*   __restrict__ symbols,  // [2048]
                        const int*   __restrict__ args,     // [2048, 2]
                        float*       __restrict__ out)      // [2048, 32, 512]
{
    __shared__ __align__(16) float2 ws2[DW * K2D];   // dup'd W[sym], 16 KB
    __shared__ float bsh[DW];
    __shared__ float sqp[4][128][4];                 // partial sq sums, 8 KB

    const int n  = blockIdx.x;
    const int t  = threadIdx.x;
    const int tg = t >> 7;        // d-group: d = 8*tg .. 8*tg+7
    const int cl = t & 127;       // owns world cols 4cl .. 4cl+3
    const int d0 = tg * 8;

    const int idx = indices[n];
    const int sym = symbols[n];
    const int a0  = args[2 * n];
    const int a1  = args[2 * n + 1];

    // Load + duplicate W[sym] into smem
    const float* Wp = W + (size_t)sym * (DW * K2D);
    #pragma unroll
    for (int i = 0; i < 4; i++) {
        int j = t + 512 * i;
        float v = Wp[j];
        ws2[j] = make_float2(v, v);
    }
    if (t < DW) bsh[t] = b[sym * DW + t];
    __syncthreads();

    // ulonglong2 view: row kk at +kk*128 units, this thread's 4 cols at +cl.
    // kk 0..31 -> left state, 32..63 -> right (pre-biased by -32 rows).
    const ulonglong2* bl  = (const ulonglong2*)(states + (size_t)(a0 * BATCH + idx) * (DW * NW)) + cl;
    const ulonglong2* br2 = (const ulonglong2*)(states + (size_t)(a1 * BATCH + idx) * (DW * NW)) + cl
                            - 32 * 128;

    // acc[dd][p]: packed col-pair p (cols 4cl+2p, 4cl+2p+1) for d = d0+dd
    uint64_t acc[8][2];
    #pragma unroll
    for (int dd = 0; dd < 8; dd++) {
        float bv = bsh[d0 + dd];
        uint64_t pb;
        asm("mov.b64 %0, {%1,%2};" : "=l"(pb) : "f"(bv), "f"(bv));
        acc[dd][0] = pb; acc[dd][1] = pb;
    }

    const float2* wbase = ws2 + d0 * K2D;

    // Double-buffered k-pair loop (32 pairs), register-resident, spill-free
    ulonglong2 A0, A1, B0, B1;
    A0 = bl[0];
    A1 = bl[128];

    #pragma unroll 1
    for (int kq = 0; kq < 32; kq += 2) {
        {   // prefetch k-pair kq+1 (rows 2kq+2, 2kq+3)
            const int kk = 2 * kq + 2;
            const ulonglong2* p = ((kk < 32) ? bl : br2) + kk * 128;
            B0 = p[0];
            B1 = p[128];
        }
        proc_kpair(acc, A0, A1, wbase + 2 * kq);

        {   // prefetch k-pair kq+2 (clamped tail: redundant reload of 62,63)
            const int kk = (kq + 2 < 32) ? (2 * kq + 4) : 62;
            const ulonglong2* p = ((kk < 32) ? bl : br2) + kk * 128;
            A0 = p[0];
            A1 = p[128];
        }
        proc_kpair(acc, B0, B1, wbase + 2 * kq + 2);
    }

    // Partial squared sums over this thread's 8 d's, per column
    float sq[4] = {0.f, 0.f, 0.f, 0.f};
    #pragma unroll
    for (int dd = 0; dd < 8; dd++) {
        float2 v0 = *(float2*)&acc[dd][0];
        float2 v1 = *(float2*)&acc[dd][1];
        sq[0] = fmaf(v0.x, v0.x, sq[0]);
        sq[1] = fmaf(v0.y, v0.y, sq[1]);
        sq[2] = fmaf(v1.x, v1.x, sq[2]);
        sq[3] = fmaf(v1.y, v1.y, sq[3]);
    }
    #pragma unroll
    for (int j = 0; j < 4; j++) sqp[tg][cl][j] = sq[j];
    __syncthreads();

    float s[4];
    #pragma unroll
    for (int j = 0; j < 4; j++) {
        float tot = sqp[0][cl][j] + sqp[1][cl][j] + sqp[2][cl][j] + sqp[3][cl][j];
        s[j] = rsqrtf(fmaxf(tot, 1e-12f));
    }

    // Scatter row = indices[n] (arange -> bijective, plain stores)
    ulonglong2* op = (ulonglong2*)(out + (size_t)idx * (DW * NW)) + cl;
    #pragma unroll
    for (int dd = 0; dd < 8; dd++) {
        float2 v0 = *(float2*)&acc[dd][0];
        float2 v1 = *(float2*)&acc[dd][1];
        float4 r = make_float4(v0.x * s[0], v0.y * s[1], v1.x * s[2], v1.y * s[3]);
        op[(size_t)(d0 + dd) * 128] = *(ulonglong2*)&r;
    }
}

extern "C" void kernel_launch(void* const* d_in, const int* in_sizes, int n_in,
                              void* d_out, int out_size) {
    const float* states  = (const float*)d_in[0];
    const float* W       = (const float*)d_in[1];
    const float* b       = (const float*)d_in[2];
    const int*   indices = (const int*)d_in[3];
    const int*   symbols = (const int*)d_in[4];
    const int*   args    = (const int*)d_in[5];
    float*       out     = (float*)d_out;

    binop_fused_kernel<<<BATCH, 512>>>(states, W, b, indices, symbols, args, out);
}

// round 8
// speedup vs baseline: 2.8301x; 2.1005x over previous
#include <cuda_runtime.h>
#include <stdint.h>

#define DW    32     // D_WORLDS
#define K2D   64
#define NW    512    // N_WORLDS
#define BATCH 2048
#define WPAD  68     // padded W row (floats): bank = (4g+tig)%32, lane-bijective

__device__ __forceinline__ uint32_t tf32_hi(float x) {
    uint32_t r; asm("cvt.rna.tf32.f32 %0, %1;" : "=r"(r) : "f"(x)); return r;
}

// D += A(tf32) * B(tf32), m16n8k8, A row-major, B col-major
#define HMMA(d, A0, A1, A2, A3, B0, B1) \
    asm volatile("mma.sync.aligned.m16n8k8.row.col.f32.tf32.tf32.f32 " \
        "{%0,%1,%2,%3}, {%4,%5,%6,%7}, {%8,%9}, {%0,%1,%2,%3};" \
        : "+f"((d)[0]), "+f"((d)[1]), "+f"((d)[2]), "+f"((d)[3]) \
        : "r"(A0), "r"(A1), "r"(A2), "r"(A3), "r"(B0), "r"(B1))

__global__ __launch_bounds__(128, 6)
void binop_mma_kernel(const float* __restrict__ states,   // [8*2048, 32, 512]
                      const float* __restrict__ W,        // [128, 32, 64]
                      const float* __restrict__ b,        // [128, 32]
                      const int*   __restrict__ indices,  // [2048]
                      const int*   __restrict__ symbols,  // [2048]
                      const int*   __restrict__ args,     // [2048, 2]
                      float*       __restrict__ out)      // [2048, 32, 512]
{
    __shared__ float wh[DW * WPAD];   // tf32-hi of W[sym][d][k]
    __shared__ float wl[DW * WPAD];   // tf32 of residual
    __shared__ float bsh[DW];

    const int n    = blockIdx.x >> 2;     // sample
    const int q    = blockIdx.x & 3;      // world-quarter (128 worlds)
    const int t    = threadIdx.x;
    const int lane = t & 31;
    const int warp = t >> 5;
    const int g    = lane >> 2;           // group id (0..7)
    const int tig  = lane & 3;            // thread in group

    const int idx = indices[n];
    const int sym = symbols[n];
    const int a0  = args[2 * n];
    const int a1  = args[2 * n + 1];

    // --- W[sym] hi/lo split into padded smem ---
    const float* Wp = W + (size_t)sym * (DW * K2D);
    #pragma unroll
    for (int i = 0; i < 16; i++) {
        int j  = t + 128 * i;              // 0..2047
        int d  = j >> 6;
        int kk = j & 63;
        float w  = Wp[j];
        uint32_t h = tf32_hi(w);
        float lo = w - __uint_as_float(h);
        wh[d * WPAD + kk] = __uint_as_float(h);
        wl[d * WPAD + kk] = __uint_as_float(tf32_hi(lo));
    }
    if (t < DW) bsh[t] = b[sym * DW + t];
    __syncthreads();

    // x rows: k 0..31 -> left sample row, 32..63 -> right (xr pre-biased)
    const float* xl = states + (size_t)(a0 * BATCH + idx) * (DW * NW);
    const float* xr = states + (size_t)(a1 * BATCH + idx) * (DW * NW) - (size_t)32 * NW;

    const int colA = q * 128 + warp * 32 + g;   // this lane's base world

    float acc[2][4][4];
    #pragma unroll
    for (int mt = 0; mt < 2; mt++)
        #pragma unroll
        for (int nt = 0; nt < 4; nt++)
            #pragma unroll
            for (int r = 0; r < 4; r++) acc[mt][nt][r] = 0.f;

    // raw A fragment loads, direct from gmem (sector-perfect 32B groups)
    #define LDRAW(r_, ks_) do { \
        const float* xp_ = (((ks_) < 4) ? xl : xr) + (size_t)(ks_) * 8 * NW + colA; \
        _Pragma("unroll") \
        for (int mt_ = 0; mt_ < 2; mt_++) { \
            const float* p_ = xp_ + mt_ * 16; \
            (r_)[mt_][0] = p_[(size_t)tig * NW]; \
            (r_)[mt_][1] = p_[(size_t)tig * NW + 8]; \
            (r_)[mt_][2] = p_[(size_t)(tig + 4) * NW]; \
            (r_)[mt_][3] = p_[(size_t)(tig + 4) * NW + 8]; \
        } \
    } while (0)

    // 3xTF32 step: split raw -> hi/lo frags, 4 B-LDS + 6 HMMA per ntile
    #define PROC(r_, ks_) do { \
        uint32_t ah_[2][4], al_[2][4]; \
        _Pragma("unroll") \
        for (int mt_ = 0; mt_ < 2; mt_++) \
            _Pragma("unroll") \
            for (int j_ = 0; j_ < 4; j_++) { \
                float x_ = (r_)[mt_][j_]; \
                uint32_t h_ = tf32_hi(x_); \
                ah_[mt_][j_] = h_; \
                al_[mt_][j_] = tf32_hi(x_ - __uint_as_float(h_)); \
            } \
        _Pragma("unroll") \
        for (int nt_ = 0; nt_ < 4; nt_++) { \
            const float* wp_ = wh + (nt_ * 8 + g) * WPAD + (ks_) * 8 + tig; \
            const float* lp_ = wl + (nt_ * 8 + g) * WPAD + (ks_) * 8 + tig; \
            uint32_t bh0_ = __float_as_uint(wp_[0]); \
            uint32_t bh1_ = __float_as_uint(wp_[4]); \
            uint32_t bl0_ = __float_as_uint(lp_[0]); \
            uint32_t bl1_ = __float_as_uint(lp_[4]); \
            _Pragma("unroll") \
            for (int mt_ = 0; mt_ < 2; mt_++) { \
                HMMA(acc[mt_][nt_], ah_[mt_][0], ah_[mt_][1], ah_[mt_][2], ah_[mt_][3], bh0_, bh1_); \
                HMMA(acc[mt_][nt_], al_[mt_][0], al_[mt_][1], al_[mt_][2], al_[mt_][3], bh0_, bh1_); \
                HMMA(acc[mt_][nt_], ah_[mt_][0], ah_[mt_][1], ah_[mt_][2], ah_[mt_][3], bl0_, bl1_); \
            } \
        } \
    } while (0)

    float rA[2][4], rB[2][4];
    LDRAW(rA, 0);

    #pragma unroll 1
    for (int ks = 0; ks < 8; ks += 2) {
        LDRAW(rB, ks + 1);
        PROC(rA, ks);
        if (ks + 2 < 8) LDRAW(rA, ks + 2);
        PROC(rB, ks + 1);
    }

    // --- epilogue: bias, L2-norm over d (quad shuffle reduce), scale, store ---
    float2 bb[4];
    #pragma unroll
    for (int nt = 0; nt < 4; nt++)
        bb[nt] = *(const float2*)&bsh[nt * 8 + 2 * tig];

    float* outb = out + (size_t)idx * (DW * NW);

    #pragma unroll
    for (int mt = 0; mt < 2; mt++) {
        float s0 = 0.f, s1 = 0.f;    // rows g, g+8 of this mtile
        #pragma unroll
        for (int nt = 0; nt < 4; nt++) {
            float y0 = acc[mt][nt][0] + bb[nt].x;
            float y1 = acc[mt][nt][1] + bb[nt].y;
            float y2 = acc[mt][nt][2] + bb[nt].x;
            float y3 = acc[mt][nt][3] + bb[nt].y;
            acc[mt][nt][0] = y0; acc[mt][nt][1] = y1;
            acc[mt][nt][2] = y2; acc[mt][nt][3] = y3;
            s0 = fmaf(y0, y0, fmaf(y1, y1, s0));
            s1 = fmaf(y2, y2, fmaf(y3, y3, s1));
        }
        s0 += __shfl_xor_sync(0xffffffffu, s0, 1);
        s0 += __shfl_xor_sync(0xffffffffu, s0, 2);
        s1 += __shfl_xor_sync(0xffffffffu, s1, 1);
        s1 += __shfl_xor_sync(0xffffffffu, s1, 2);
        const float r0 = rsqrtf(fmaxf(s0, 1e-12f));
        const float r1 = rsqrtf(fmaxf(s1, 1e-12f));

        float* op = outb + colA + mt * 16;
        #pragma unroll
        for (int nt = 0; nt < 4; nt++) {
            const int nrow = nt * 8 + 2 * tig;
            op[(size_t)nrow * NW]           = acc[mt][nt][0] * r0;
            op[(size_t)(nrow + 1) * NW]     = acc[mt][nt][1] * r0;
            op[(size_t)nrow * NW + 8]       = acc[mt][nt][2] * r1;
            op[(size_t)(nrow + 1) * NW + 8] = acc[mt][nt][3] * r1;
        }
    }
}

extern "C" void kernel_launch(void* const* d_in, const int* in_sizes, int n_in,
                              void* d_out, int out_size) {
    const float* states  = (const float*)d_in[0];
    const float* W       = (const float*)d_in[1];
    const float* b       = (const float*)d_in[2];
    const int*   indices = (const int*)d_in[3];
    const int*   symbols = (const int*)d_in[4];
    const int*   args    = (const int*)d_in[5];
    float*       out     = (float*)d_out;

    binop_mma_kernel<<<BATCH * 4, 128>>>(states, W, b, indices, symbols, args, out);
}